// round 8
// baseline (speedup 1.0000x reference)
#include <cuda_runtime.h>
#include <cuda_bf16.h>
#include <math.h>

// Problem constants
#define NTOK   8192
#define DIM    256
#define HH     8
#define HD     32
#define WW     64
#define NW     128          // NTOK / WW
#define T6     216          // 3*40 + 3*32
#define QSCALE 0.17677669529663687f   // 32^-0.5

typedef unsigned long long u64;

// ---- packed f32x2 helpers (sm_100+) ----
__device__ __forceinline__ void ffma2(u64 &c, u64 a, u64 b) {
    asm("fma.rn.f32x2 %0, %1, %2, %0;" : "+l"(c) : "l"(a), "l"(b));
}
__device__ __forceinline__ u64 pk2(float lo, float hi) {
    u64 r; asm("mov.b64 %0, {%1, %2};" : "=l"(r) : "f"(lo), "f"(hi)); return r;
}
__device__ __forceinline__ float2 up2(u64 v) {
    float2 r; asm("mov.b64 {%0, %1}, %2;" : "=f"(r.x), "=f"(r.y) : "l"(v)); return r;
}
__device__ __forceinline__ float hsum2(u64 v) { float2 p = up2(v); return p.x + p.y; }

// Global scratch (static device allocations -- allowed)
__device__ float g_q[NTOK * DIM];
__device__ float g_k[NTOK * DIM];
__device__ float g_v[NTOK * DIM];
__device__ float g_att[NTOK * DIM];

// ---------------------------------------------------------------------------
// QKV GEMM: BM=128 BN=128 BK=16, 256 threads, 8x8 via f32x2, double-buffered.
// ---------------------------------------------------------------------------
__global__ __launch_bounds__(256) void qkv_gemm_kernel(
    const float* __restrict__ A, const float* __restrict__ Wt,
    const float* __restrict__ bias)
{
    __shared__ __align__(16) float As[2][16][132];
    __shared__ __align__(16) float Bs[2][16][132];
    const int m0 = blockIdx.x * 128, n0 = blockIdx.y * 128;
    const int tid = threadIdx.x;
    const int tx = tid & 15, ty = tid >> 4;
    const int lr = tid >> 1, lc = (tid & 1) * 8;

    u64 c2[8][4];
#pragma unroll
    for (int i = 0; i < 8; i++)
#pragma unroll
        for (int j = 0; j < 4; j++) c2[i][j] = pk2(0.f, 0.f);

    const float* Arow = A  + (m0 + lr) * 256 + lc;
    const float* Brow = Wt + (n0 + lr) * 256 + lc;

    {
        float4 a0 = *(const float4*)(Arow);
        float4 a1 = *(const float4*)(Arow + 4);
        float4 b0 = *(const float4*)(Brow);
        float4 b1 = *(const float4*)(Brow + 4);
        As[0][lc + 0][lr] = a0.x; As[0][lc + 1][lr] = a0.y;
        As[0][lc + 2][lr] = a0.z; As[0][lc + 3][lr] = a0.w;
        As[0][lc + 4][lr] = a1.x; As[0][lc + 5][lr] = a1.y;
        As[0][lc + 6][lr] = a1.z; As[0][lc + 7][lr] = a1.w;
        Bs[0][lc + 0][lr] = b0.x; Bs[0][lc + 1][lr] = b0.y;
        Bs[0][lc + 2][lr] = b0.z; Bs[0][lc + 3][lr] = b0.w;
        Bs[0][lc + 4][lr] = b1.x; Bs[0][lc + 5][lr] = b1.y;
        Bs[0][lc + 6][lr] = b1.z; Bs[0][lc + 7][lr] = b1.w;
    }
    __syncthreads();

    for (int step = 0; step < 16; step++) {
        const int cur = step & 1, nxt = cur ^ 1;
        float4 na0, na1, nb0, nb1;
        if (step < 15) {
            const int kk = (step + 1) * 16;
            na0 = *(const float4*)(Arow + kk);
            na1 = *(const float4*)(Arow + kk + 4);
            nb0 = *(const float4*)(Brow + kk);
            nb1 = *(const float4*)(Brow + kk + 4);
        }
#pragma unroll
        for (int k = 0; k < 16; k++) {
            float4 av0 = *(const float4*)&As[cur][k][ty * 4];
            float4 av1 = *(const float4*)&As[cur][k][64 + ty * 4];
            ulonglong2 bl = *(const ulonglong2*)&Bs[cur][k][tx * 4];
            ulonglong2 bh = *(const ulonglong2*)&Bs[cur][k][64 + tx * 4];
            u64 bb[4] = {bl.x, bl.y, bh.x, bh.y};
            float aa[8] = {av0.x, av0.y, av0.z, av0.w,
                           av1.x, av1.y, av1.z, av1.w};
#pragma unroll
            for (int i = 0; i < 8; i++) {
                u64 ad = pk2(aa[i], aa[i]);
#pragma unroll
                for (int j = 0; j < 4; j++) ffma2(c2[i][j], ad, bb[j]);
            }
        }
        if (step < 15) {
            As[nxt][lc + 0][lr] = na0.x; As[nxt][lc + 1][lr] = na0.y;
            As[nxt][lc + 2][lr] = na0.z; As[nxt][lc + 3][lr] = na0.w;
            As[nxt][lc + 4][lr] = na1.x; As[nxt][lc + 5][lr] = na1.y;
            As[nxt][lc + 6][lr] = na1.z; As[nxt][lc + 7][lr] = na1.w;
            Bs[nxt][lc + 0][lr] = nb0.x; Bs[nxt][lc + 1][lr] = nb0.y;
            Bs[nxt][lc + 2][lr] = nb0.z; Bs[nxt][lc + 3][lr] = nb0.w;
            Bs[nxt][lc + 4][lr] = nb1.x; Bs[nxt][lc + 5][lr] = nb1.y;
            Bs[nxt][lc + 6][lr] = nb1.z; Bs[nxt][lc + 7][lr] = nb1.w;
            __syncthreads();
        }
    }

#pragma unroll
    for (int i = 0; i < 8; i++) {
        int m = m0 + ((i < 4) ? (ty * 4 + i) : (64 + ty * 4 + i - 4));
#pragma unroll
        for (int g = 0; g < 2; g++) {
            int n = n0 + g * 64 + tx * 4;
            float2 p0 = up2(c2[i][g * 2]);
            float2 p1 = up2(c2[i][g * 2 + 1]);
            float4 b4 = *(const float4*)&bias[n];
            float4 o;
            o.x = p0.x + b4.x; o.y = p0.y + b4.y;
            o.z = p1.x + b4.z; o.w = p1.y + b4.w;
            int s = n >> 8, col = n & 255;
            float* dst;
            if (s == 0) {
                o.x *= QSCALE; o.y *= QSCALE; o.z *= QSCALE; o.w *= QSCALE;
                dst = g_q;
            } else if (s == 1) dst = g_k;
            else               dst = g_v;
            *(float4*)&dst[m * 256 + col] = o;
        }
    }
}

// ---------------------------------------------------------------------------
// Projection GEMM, same structure (double-buffered)
// ---------------------------------------------------------------------------
__global__ __launch_bounds__(256) void proj_gemm_kernel(
    const float* __restrict__ Wt, const float* __restrict__ bias,
    float* __restrict__ out)
{
    __shared__ __align__(16) float As[2][16][132];
    __shared__ __align__(16) float Bs[2][16][132];
    const int m0 = blockIdx.x * 128, n0 = blockIdx.y * 128;
    const int tid = threadIdx.x;
    const int tx = tid & 15, ty = tid >> 4;
    const int lr = tid >> 1, lc = (tid & 1) * 8;

    u64 c2[8][4];
#pragma unroll
    for (int i = 0; i < 8; i++)
#pragma unroll
        for (int j = 0; j < 4; j++) c2[i][j] = pk2(0.f, 0.f);

    const float* Arow = g_att + (m0 + lr) * 256 + lc;
    const float* Brow = Wt    + (n0 + lr) * 256 + lc;

    {
        float4 a0 = *(const float4*)(Arow);
        float4 a1 = *(const float4*)(Arow + 4);
        float4 b0 = *(const float4*)(Brow);
        float4 b1 = *(const float4*)(Brow + 4);
        As[0][lc + 0][lr] = a0.x; As[0][lc + 1][lr] = a0.y;
        As[0][lc + 2][lr] = a0.z; As[0][lc + 3][lr] = a0.w;
        As[0][lc + 4][lr] = a1.x; As[0][lc + 5][lr] = a1.y;
        As[0][lc + 6][lr] = a1.z; As[0][lc + 7][lr] = a1.w;
        Bs[0][lc + 0][lr] = b0.x; Bs[0][lc + 1][lr] = b0.y;
        Bs[0][lc + 2][lr] = b0.z; Bs[0][lc + 3][lr] = b0.w;
        Bs[0][lc + 4][lr] = b1.x; Bs[0][lc + 5][lr] = b1.y;
        Bs[0][lc + 6][lr] = b1.z; Bs[0][lc + 7][lr] = b1.w;
    }
    __syncthreads();

    for (int step = 0; step < 16; step++) {
        const int cur = step & 1, nxt = cur ^ 1;
        float4 na0, na1, nb0, nb1;
        if (step < 15) {
            const int kk = (step + 1) * 16;
            na0 = *(const float4*)(Arow + kk);
            na1 = *(const float4*)(Arow + kk + 4);
            nb0 = *(const float4*)(Brow + kk);
            nb1 = *(const float4*)(Brow + kk + 4);
        }
#pragma unroll
        for (int k = 0; k < 16; k++) {
            float4 av0 = *(const float4*)&As[cur][k][ty * 4];
            float4 av1 = *(const float4*)&As[cur][k][64 + ty * 4];
            ulonglong2 bl = *(const ulonglong2*)&Bs[cur][k][tx * 4];
            ulonglong2 bh = *(const ulonglong2*)&Bs[cur][k][64 + tx * 4];
            u64 bb[4] = {bl.x, bl.y, bh.x, bh.y};
            float aa[8] = {av0.x, av0.y, av0.z, av0.w,
                           av1.x, av1.y, av1.z, av1.w};
#pragma unroll
            for (int i = 0; i < 8; i++) {
                u64 ad = pk2(aa[i], aa[i]);
#pragma unroll
                for (int j = 0; j < 4; j++) ffma2(c2[i][j], ad, bb[j]);
            }
        }
        if (step < 15) {
            As[nxt][lc + 0][lr] = na0.x; As[nxt][lc + 1][lr] = na0.y;
            As[nxt][lc + 2][lr] = na0.z; As[nxt][lc + 3][lr] = na0.w;
            As[nxt][lc + 4][lr] = na1.x; As[nxt][lc + 5][lr] = na1.y;
            As[nxt][lc + 6][lr] = na1.z; As[nxt][lc + 7][lr] = na1.w;
            Bs[nxt][lc + 0][lr] = nb0.x; Bs[nxt][lc + 1][lr] = nb0.y;
            Bs[nxt][lc + 2][lr] = nb0.z; Bs[nxt][lc + 3][lr] = nb0.w;
            Bs[nxt][lc + 4][lr] = nb1.x; Bs[nxt][lc + 5][lr] = nb1.y;
            Bs[nxt][lc + 6][lr] = nb1.z; Bs[nxt][lc + 7][lr] = nb1.w;
            __syncthreads();
        }
    }

#pragma unroll
    for (int i = 0; i < 8; i++) {
        int m = m0 + ((i < 4) ? (ty * 4 + i) : (64 + ty * 4 + i - 4));
#pragma unroll
        for (int g = 0; g < 2; g++) {
            int n = n0 + g * 64 + tx * 4;
            float2 p0 = up2(c2[i][g * 2]);
            float2 p1 = up2(c2[i][g * 2 + 1]);
            float4 b4 = *(const float4*)&bias[n];
            float4 o;
            o.x = p0.x + b4.x; o.y = p0.y + b4.y;
            o.z = p1.x + b4.z; o.w = p1.y + b4.w;
            *(float4*)&out[m * 256 + n] = o;
        }
    }
}

// ---------------------------------------------------------------------------
// Attention kernel: one block per (window, head). 512 threads (16 warps).
// Shared layout (floats), total 53568 floats = 214272 B:
//   scw   [384]       @ 0
//   sq    [64*36]     @ 384     (stride 36: 16B-aligned, phase-conflict-free)
//   sk    [64*36]     @ 2688
//   svT   [32*66]     @ 4992    (d-major, stride 66: 8B-aligned lanes)
//   stabQ [216*32]    @ 7104    (dead after Dq/Dk; s_idx u64[4096] aliases)
//   stabK [216*32]    @ 14016
//   sdq   [64*221]    @ 20928   (stride 221: conflict-free STS; dead after
//   sdk   [64*221]    @ 35072    logits -> satT[216*68]@20928, vtabT@35616)
//   slogT [64*68]     @ 49216   (j-major: slogT[j][i])
// ---------------------------------------------------------------------------
#define SM_FLOATS 53568
#define SMEM_BYTES (SM_FLOATS * 4)

__global__ __launch_bounds__(512) void attn_kernel(
    const float* __restrict__ n_coords,
    const float* __restrict__ qx, const float* __restrict__ kx,
    const float* __restrict__ vx,
    const float* __restrict__ qr, const float* __restrict__ kr,
    const float* __restrict__ vr)
{
    extern __shared__ __align__(16) float sm[];
    float* scw   = sm;
    float* sq    = sm + 384;     // stride 36
    float* sk    = sm + 2688;    // stride 36
    float* svT   = sm + 4992;    // stride 66
    float* stabQ = sm + 7104;
    float* stabK = sm + 14016;
    float* sdq   = sm + 20928;   // stride 221
    float* sdk   = sm + 35072;   // stride 221
    float* slogT = sm + 49216;   // stride 68, [j][i]
    float* satT  = sm + 20928;   // stride 68, [t][i]  (aliases sdq/sdk head)
    float* vtabT = sm + 35616;   // stride 218, [d][t] (aliases sdk tail)
    u64*   s_idx = (u64*)(sm + 7104);   // u64[4096] over stabQ/K (after Dq/Dk)

    const int nb = blockIdx.x, h = blockIdx.y;
    const int tid = threadIdx.x;
    const int l = tid & 31, w = tid >> 5;
    const int tok0 = nb * WW;

    // ---- load coords, q, k, v(T), both tables ----
    for (int s = tid; s < WW * 6; s += 512) {
        int i = s / 6, c = s % 6;
        scw[s] = n_coords[(tok0 + i) * 6 + c] * (c < 3 ? 4.0f : 8.0f);
    }
    for (int s = tid; s < WW * HD; s += 512) {
        int i = s >> 5, d = s & 31;
        int g = (tok0 + i) * 256 + h * 32 + d;
        sq[i * 36 + d]  = g_q[g];
        sk[i * 36 + d]  = g_k[g];
        svT[d * 66 + i] = g_v[g];
    }
    for (int s = tid; s < T6 * HD; s += 512) {
        int t = s >> 5, d = s & 31;
        stabQ[s] = (t < 120) ? qx[(t * 8 + h) * 32 + d]
                             : qr[((t - 120) * 8 + h) * 32 + d];
        stabK[s] = (t < 120) ? kx[(t * 8 + h) * 32 + d]
                             : kr[((t - 120) * 8 + h) * 32 + d];
    }
    __syncthreads();

    // ---- Dq / Dk : i = tid&63, each of 8 groups covers 27 t ----
    {
        const int i = tid & 63, grp = tid >> 6;
        const int t0 = grp * 27, t1 = t0 + 27;
        u64 a2[16];
        {
            const ulonglong2* qp = (const ulonglong2*)(sq + i * 36);
#pragma unroll
            for (int d4 = 0; d4 < 8; d4++) {
                ulonglong2 v = qp[d4];
                a2[2 * d4] = v.x; a2[2 * d4 + 1] = v.y;
            }
        }
        for (int t = t0; t < t1; t++) {
            const ulonglong2* tv = (const ulonglong2*)(stabQ + t * 32);
            u64 acc = pk2(0.f, 0.f);
#pragma unroll
            for (int d4 = 0; d4 < 8; d4++) {
                ulonglong2 tt = tv[d4];
                ffma2(acc, a2[2 * d4],     tt.x);
                ffma2(acc, a2[2 * d4 + 1], tt.y);
            }
            sdq[i * 221 + t] = hsum2(acc);
        }
        {
            const ulonglong2* kp = (const ulonglong2*)(sk + i * 36);
#pragma unroll
            for (int d4 = 0; d4 < 8; d4++) {
                ulonglong2 v = kp[d4];
                a2[2 * d4] = v.x; a2[2 * d4 + 1] = v.y;
            }
        }
        for (int t = t0; t < t1; t++) {
            const ulonglong2* tv = (const ulonglong2*)(stabK + t * 32);
            u64 acc = pk2(0.f, 0.f);
#pragma unroll
            for (int d4 = 0; d4 < 8; d4++) {
                ulonglong2 tt = tv[d4];
                ffma2(acc, a2[2 * d4],     tt.x);
                ffma2(acc, a2[2 * d4 + 1], tt.y);
            }
            sdk[i * 221 + t] = hsum2(acc);
        }
    }
    __syncthreads();

    // ---- logits: k-row hoisted in regs, reused across 4 query rows ----
    {
        const int basec[6] = {0, 40, 80, 120, 152, 184};
        const int offc[6]  = {20, 20, 20, 16, 16, 16};
        const int hic[6]   = {39, 39, 39, 31, 31, 31};
        float cir[4][6];
#pragma unroll
        for (int r = 0; r < 4; r++)
#pragma unroll
            for (int c = 0; c < 6; c++) cir[r][c] = scw[(w * 4 + r) * 6 + c];

#pragma unroll
        for (int jj = 0; jj < 2; jj++) {
            const int j = l + jj * 32;
            u64 kr2[16];
            {
                const ulonglong2* kp = (const ulonglong2*)(sk + j * 36);
#pragma unroll
                for (int d4 = 0; d4 < 8; d4++) {
                    ulonglong2 v = kp[d4];
                    kr2[2 * d4] = v.x; kr2[2 * d4 + 1] = v.y;
                }
            }
            float cj[6];
#pragma unroll
            for (int c = 0; c < 6; c++) cj[c] = scw[j * 6 + c];

#pragma unroll
            for (int r = 0; r < 4; r++) {
                const int i = w * 4 + r;
                const ulonglong2* qp = (const ulonglong2*)(sq + i * 36);
                u64 acc2 = pk2(0.f, 0.f);
#pragma unroll
                for (int d4 = 0; d4 < 8; d4++) {
                    ulonglong2 qq = qp[d4];
                    ffma2(acc2, qq.x, kr2[2 * d4]);
                    ffma2(acc2, qq.y, kr2[2 * d4 + 1]);
                }
                float acc = hsum2(acc2);
                u64 pack = 0;
#pragma unroll
                for (int c = 0; c < 6; c++) {
                    int id = (int)floorf(cir[r][c] - cj[c]) + offc[c];
                    id = min(max(id, 0), hic[c]);
                    int t = basec[c] + id;
                    acc += sdq[i * 221 + t] + sdk[j * 221 + t];
                    pack |= (u64)t << (8 * c);
                }
                slogT[j * 68 + i] = acc;
                s_idx[i * 64 + j] = pack;
            }
        }
    }
    __syncthreads();   // logits reads of sdq/sdk complete; satT/vtabT may alias

    // ---- zero satT bins, load v-table (transposed, stride 218) ----
    for (int s = tid; s < T6 * 68; s += 512) satT[s] = 0.f;
    for (int s = tid; s < T6 * HD; s += 512) {
        int t = s >> 5, d = s & 31;
        float val = (t < 120) ? vx[(t * 8 + h) * 32 + d]
                              : vr[((t - 120) * 8 + h) * 32 + d];
        vtabT[d * 218 + t] = val;
    }
    __syncthreads();

    // ---- softmax (own rows per warp), normalize in slogT ----
#pragma unroll
    for (int r = 0; r < 4; r++) {
        int i = w * 4 + r;
        float v0 = slogT[l * 68 + i], v1 = slogT[(l + 32) * 68 + i];
        float m = fmaxf(v0, v1);
#pragma unroll
        for (int o = 16; o > 0; o >>= 1)
            m = fmaxf(m, __shfl_xor_sync(0xffffffffu, m, o));
        float e0 = __expf(v0 - m), e1 = __expf(v1 - m);
        float s = e0 + e1;
#pragma unroll
        for (int o = 16; o > 0; o >>= 1)
            s += __shfl_xor_sync(0xffffffffu, s, o);
        float inv = 1.0f / s;
        slogT[l * 68 + i]        = e0 * inv;
        slogT[(l + 32) * 68 + i] = e1 * inv;
    }
    __syncwarp();

    // ---- atomic-free binning: lane owns (row, coord) -> disjoint bins ----
    if (l < 24) {
        int r = l / 6, c = l % 6;
        int i = w * 4 + r;
        const u64* ip = s_idx + i * 64;
        const int sh = 8 * c;
        for (int j = 0; j < 64; j++) {
            int t = (int)((ip[j] >> sh) & 255u);
            satT[t * 68 + i] += slogT[j * 68 + i];
        }
    }
    __syncwarp();

    // ---- out[i][d] = attn @ v + at @ vtab ----
    // lane = d; bcast LDS.128 serves 4 rows; v loads as LDS.64 (float2).
    {
        const int i0 = w * 4;
        u64 acc01 = pk2(0.f, 0.f), acc23 = pk2(0.f, 0.f);
        const float2* svrow2 = (const float2*)(svT + l * 66);
#pragma unroll 8
        for (int j2 = 0; j2 < 32; j2++) {
            float2 v = svrow2[j2];
            float4 a0 = *(const float4*)&slogT[(2 * j2) * 68 + i0];
            float4 a1 = *(const float4*)&slogT[(2 * j2 + 1) * 68 + i0];
            u64 vd0 = pk2(v.x, v.x), vd1 = pk2(v.y, v.y);
            ffma2(acc01, pk2(a0.x, a0.y), vd0);
            ffma2(acc23, pk2(a0.z, a0.w), vd0);
            ffma2(acc01, pk2(a1.x, a1.y), vd1);
            ffma2(acc23, pk2(a1.z, a1.w), vd1);
        }
        const float2* vtrow2 = (const float2*)(vtabT + l * 218);
#pragma unroll 6
        for (int t2 = 0; t2 < 108; t2++) {
            float2 v = vtrow2[t2];
            float4 a0 = *(const float4*)&satT[(2 * t2) * 68 + i0];
            float4 a1 = *(const float4*)&satT[(2 * t2 + 1) * 68 + i0];
            u64 vd0 = pk2(v.x, v.x), vd1 = pk2(v.y, v.y);
            ffma2(acc01, pk2(a0.x, a0.y), vd0);
            ffma2(acc23, pk2(a0.z, a0.w), vd0);
            ffma2(acc01, pk2(a1.x, a1.y), vd1);
            ffma2(acc23, pk2(a1.z, a1.w), vd1);
        }
        float2 o01 = up2(acc01), o23 = up2(acc23);
        const int ob = (tok0 + i0) * 256 + h * 32 + l;
        g_att[ob]       = o01.x;
        g_att[ob + 256] = o01.y;
        g_att[ob + 512] = o23.x;
        g_att[ob + 768] = o23.y;
    }
}

// ---------------------------------------------------------------------------
extern "C" void kernel_launch(void* const* d_in, const int* in_sizes, int n_in,
                              void* d_out, int out_size)
{
    const float* feats    = (const float*)d_in[0];
    const float* n_coords = (const float*)d_in[1];
    const float* qkv_w    = (const float*)d_in[2];
    const float* qkv_b    = (const float*)d_in[3];
    const float* qx       = (const float*)d_in[4];
    const float* kx       = (const float*)d_in[5];
    const float* vx       = (const float*)d_in[6];
    const float* qr       = (const float*)d_in[7];
    const float* kr       = (const float*)d_in[8];
    const float* vr       = (const float*)d_in[9];
    const float* pw       = (const float*)d_in[10];
    const float* pb       = (const float*)d_in[11];
    float* out = (float*)d_out;

    cudaFuncSetAttribute(attn_kernel,
                         cudaFuncAttributeMaxDynamicSharedMemorySize,
                         SMEM_BYTES);

    qkv_gemm_kernel<<<dim3(64, 6), 256>>>(feats, qkv_w, qkv_b);
    attn_kernel<<<dim3(NW, HH), 512, SMEM_BYTES>>>(n_coords, qx, kx, vx,
                                                   qr, kr, vr);
    proj_gemm_kernel<<<dim3(64, 2), 256>>>(pw, pb, out);
}